// round 2
// baseline (speedup 1.0000x reference)
#include <cuda_runtime.h>
#include <float.h>

#define KNN      8
#define THREADS  128
#define CHUNK    2048   // refs per smem tile: 2048 * 16B = 32 KB

// Streaming top-8 insertion (sorted ascending, strict < keeps earlier index on
// ties, matching jax top_k tie order). Fully unrolled -> stays in registers.
__device__ __forceinline__ void insert8(float (&bd)[KNN], int (&bi)[KNN], float d, int id) {
#pragma unroll
    for (int k = 0; k < KNN; k++) {
        if (d < bd[k]) {
            float td = bd[k]; int ti = bi[k];
            bd[k] = d; bi[k] = id;
            d = td; id = ti;
        }
    }
}

__global__ __launch_bounds__(THREADS)
void knn_idw_kernel(const float* __restrict__ qpts,
                    const float* __restrict__ rpts,
                    const float* __restrict__ rflow,
                    float* __restrict__ out,
                    int N, int M)
{
    __shared__ float4 s_ref[CHUNK];   // (x, y, z, |r|^2)

    const int tid = threadIdx.x;
    const int qi  = blockIdx.x * THREADS + tid;

    float qx = 0.f, qy = 0.f, qz = 0.f;
    if (qi < N) {
        qx = qpts[3 * qi + 0];
        qy = qpts[3 * qi + 1];
        qz = qpts[3 * qi + 2];
    }
    // ranking key: s = |r|^2 - 2 q.r   (|q|^2 is a per-query constant -> added back in epilogue)
    const float ax = -2.f * qx, ay = -2.f * qy, az = -2.f * qz;

    float bd[KNN]; int bi[KNN];
#pragma unroll
    for (int k = 0; k < KNN; k++) { bd[k] = FLT_MAX; bi[k] = 0; }

    for (int base = 0; base < M; base += CHUNK) {
        const int cnt = min(CHUNK, M - base);
        __syncthreads();
        // cooperative tile load: pack (x,y,z,r2) so the hot loop is 1 LDS.128/ref
        for (int j = tid; j < cnt; j += THREADS) {
            const float* rp = rpts + 3 * (base + j);
            float x = __ldg(rp + 0);
            float y = __ldg(rp + 1);
            float z = __ldg(rp + 2);
            s_ref[j] = make_float4(x, y, z, fmaf(x, x, fmaf(y, y, z * z)));
        }
        __syncthreads();

        int j = 0;
        // hot loop: groups of 8, one top-8 test per group via min-tree
        for (; j + 8 <= cnt; j += 8) {
            float s[8];
#pragma unroll
            for (int u = 0; u < 8; u++) {
                float4 rp = s_ref[j + u];                    // warp-broadcast LDS.128
                s[u] = fmaf(ax, rp.x, fmaf(ay, rp.y, fmaf(az, rp.z, rp.w)));
            }
            float m01 = fminf(s[0], s[1]);
            float m23 = fminf(s[2], s[3]);
            float m45 = fminf(s[4], s[5]);
            float m67 = fminf(s[6], s[7]);
            float m   = fminf(fminf(m01, m23), fminf(m45, m67));
            if (m < bd[KNN - 1]) {               // rare path (~K/rank decay)
#pragma unroll
                for (int u = 0; u < 8; u++) {
                    if (s[u] < bd[KNN - 1]) insert8(bd, bi, s[u], base + j + u);
                }
            }
        }
        // remainder (not taken for M=16384, kept for generality)
        for (; j < cnt; j++) {
            float4 rp = s_ref[j];
            float sv = fmaf(ax, rp.x, fmaf(ay, rp.y, fmaf(az, rp.z, rp.w)));
            if (sv < bd[KNN - 1]) insert8(bd, bi, sv, base + j);
        }
    }

    if (qi >= N) return;

    // epilogue: d2 = s + |q|^2 (clamped), w = 1/(d2+eps)  [sqrt cancels: POWER==2]
    const float q2 = fmaf(qx, qx, fmaf(qy, qy, qz * qz));
    float sumw = 0.f, fx = 0.f, fy = 0.f, fz = 0.f;
#pragma unroll
    for (int k = 0; k < KNN; k++) {
        float d2 = fmaxf(bd[k] + q2, 0.0f);
        float w  = 1.0f / (d2 + 1e-8f);
        sumw += w;
        const float* f = rflow + 3 * bi[k];
        fx = fmaf(w, __ldg(f + 0), fx);
        fy = fmaf(w, __ldg(f + 1), fy);
        fz = fmaf(w, __ldg(f + 2), fz);
    }
    const float inv = 1.0f / sumw;
    out[3 * qi + 0] = fx * inv;
    out[3 * qi + 1] = fy * inv;
    out[3 * qi + 2] = fz * inv;
}

extern "C" void kernel_launch(void* const* d_in, const int* in_sizes, int n_in,
                              void* d_out, int out_size)
{
    const float* qpts  = (const float*)d_in[0];   // [N,3] float32
    const float* rpts  = (const float*)d_in[1];   // [M,3] float32
    const float* rflow = (const float*)d_in[2];   // [M,3] float32
    float* out = (float*)d_out;                   // [N,3] float32

    const int N = in_sizes[0] / 3;
    const int M = in_sizes[1] / 3;

    const int grid = (N + THREADS - 1) / THREADS;
    knn_idw_kernel<<<grid, THREADS>>>(qpts, rpts, rflow, out, N, M);
}

// round 3
// speedup vs baseline: 1.6020x; 1.6020x over previous
#include <cuda_runtime.h>
#include <float.h>

#define KNN      8
#define THREADS  512          // 4 subgroups x 128 query-threads
#define NSPLIT   4            // M-dimension split inside the CTA
#define QPB      128          // queries per block
#define SCHUNK   512          // refs per subgroup tile (4 x 512 x 16B = 32KB)
#define MGW      (NSPLIT*KNN + 1)   // merge row stride (33 floats) -> conflict-free

// Streaming top-8 insertion (sorted ascending; strict < keeps earlier index on
// ties, matching jax top_k tie order).
__device__ __forceinline__ void insert8(float (&bd)[KNN], int (&bi)[KNN], float d, int id) {
#pragma unroll
    for (int k = 0; k < KNN; k++) {
        if (d < bd[k]) {
            float td = bd[k]; int ti = bi[k];
            bd[k] = d; bi[k] = id;
            d = td; id = ti;
        }
    }
}

__global__ __launch_bounds__(THREADS, 2)
void knn_idw_kernel(const float* __restrict__ qpts,
                    const float* __restrict__ rpts,
                    const float* __restrict__ rflow,
                    float* __restrict__ out,
                    int N, int M)
{
    __shared__ union {
        float4 tile[NSPLIT][SCHUNK];              // 32 KB  (phase 1)
        struct {                                   // 33.8 KB (phase 2, after sync)
            float d[QPB][MGW];
            int   i[QPB][MGW];
        } mg;
    } sm;

    const int tid = threadIdx.x;
    const int sg  = tid >> 7;          // subgroup 0..3 (which M-quarter)
    const int qt  = tid & 127;         // query slot within block
    const int qi  = blockIdx.x * QPB + qt;

    float qx = 0.f, qy = 0.f, qz = 0.f;
    if (qi < N) {
        qx = qpts[3 * qi + 0];
        qy = qpts[3 * qi + 1];
        qz = qpts[3 * qi + 2];
    }
    // ranking key: s = |r|^2 - 2 q.r  (|q|^2 is per-query constant, added in epilogue)
    const float ax = -2.f * qx, ay = -2.f * qy, az = -2.f * qz;

    const int Mper   = (M + NSPLIT - 1) / NSPLIT;
    const int mybase = sg * Mper;
    const int myend  = min(M, mybase + Mper);

    float bd[KNN]; int bi[KNN];
#pragma unroll
    for (int k = 0; k < KNN; k++) { bd[k] = FLT_MAX; bi[k] = 0; }

    for (int base = 0; base < Mper; base += SCHUNK) {
        const int gbase = mybase + base;
        const int cnt   = min(SCHUNK, myend - gbase);   // may be <= 0 on ragged tails
        __syncthreads();
        // each subgroup loads its own tile: pack (x,y,z,|r|^2)
        for (int j = qt; j < cnt; j += 128) {
            const float* rp = rpts + 3 * (gbase + j);
            float x = __ldg(rp + 0);
            float y = __ldg(rp + 1);
            float z = __ldg(rp + 2);
            sm.tile[sg][j] = make_float4(x, y, z, fmaf(x, x, fmaf(y, y, z * z)));
        }
        __syncthreads();

        const float4* __restrict__ p = sm.tile[sg];
        int j = 0;
        for (; j + 8 <= cnt; j += 8) {
            float s[8];
#pragma unroll
            for (int u = 0; u < 8; u++) {
                float4 rp = p[j + u];                       // warp-broadcast LDS.128
                s[u] = fmaf(ax, rp.x, fmaf(ay, rp.y, fmaf(az, rp.z, rp.w)));
            }
            float m = fminf(fminf(fminf(s[0], s[1]), fminf(s[2], s[3])),
                            fminf(fminf(s[4], s[5]), fminf(s[6], s[7])));
            if (m < bd[KNN - 1]) {                          // rare group-level slow path
#pragma unroll
                for (int u = 0; u < 8; u++) {
                    if (s[u] < bd[KNN - 1]) insert8(bd, bi, s[u], gbase + j + u);
                }
            }
        }
        for (; j < cnt; j++) {
            float4 rp = p[j];
            float sv = fmaf(ax, rp.x, fmaf(ay, rp.y, fmaf(az, rp.z, rp.w)));
            if (sv < bd[KNN - 1]) insert8(bd, bi, sv, gbase + j);
        }
    }

    // ---- merge phase: publish 4 partial top-8 lists per query, subgroup 0 reduces ----
    __syncthreads();            // all tile reads done before union is reused
#pragma unroll
    for (int k = 0; k < KNN; k++) {
        sm.mg.d[qt][sg * KNN + k] = bd[k];
        sm.mg.i[qt][sg * KNN + k] = bi[k];
    }
    __syncthreads();

    if (sg == 0 && qi < N) {
        float fd[KNN]; int fi[KNN];
#pragma unroll
        for (int k = 0; k < KNN; k++) { fd[k] = FLT_MAX; fi[k] = 0; }
        // insert in ascending chunk order -> strict < preserves lowest-index tie rule
#pragma unroll 4
        for (int c = 0; c < NSPLIT * KNN; c++) {
            float d = sm.mg.d[qt][c];
            if (d < fd[KNN - 1]) insert8(fd, fi, d, sm.mg.i[qt][c]);
        }

        // epilogue: d2 = s + |q|^2 (clamped), w = 1/(d2+eps)   [sqrt cancels: POWER==2]
        const float q2 = fmaf(qx, qx, fmaf(qy, qy, qz * qz));
        float sumw = 0.f, fx = 0.f, fy = 0.f, fz = 0.f;
#pragma unroll
        for (int k = 0; k < KNN; k++) {
            float d2 = fmaxf(fd[k] + q2, 0.0f);
            float w  = 1.0f / (d2 + 1e-8f);
            sumw += w;
            const float* f = rflow + 3 * fi[k];
            fx = fmaf(w, __ldg(f + 0), fx);
            fy = fmaf(w, __ldg(f + 1), fy);
            fz = fmaf(w, __ldg(f + 2), fz);
        }
        const float inv = 1.0f / sumw;
        out[3 * qi + 0] = fx * inv;
        out[3 * qi + 1] = fy * inv;
        out[3 * qi + 2] = fz * inv;
    }
}

extern "C" void kernel_launch(void* const* d_in, const int* in_sizes, int n_in,
                              void* d_out, int out_size)
{
    const float* qpts  = (const float*)d_in[0];   // [N,3] float32
    const float* rpts  = (const float*)d_in[1];   // [M,3] float32
    const float* rflow = (const float*)d_in[2];   // [M,3] float32
    float* out = (float*)d_out;                   // [N,3] float32

    const int N = in_sizes[0] / 3;
    const int M = in_sizes[1] / 3;

    const int grid = (N + QPB - 1) / QPB;
    knn_idw_kernel<<<grid, THREADS>>>(qpts, rpts, rflow, out, N, M);
}

// round 5
// speedup vs baseline: 2.5904x; 1.6170x over previous
#include <cuda_runtime.h>
#include <float.h>

#define KNN      8
#define THREADS  512          // 4 subgroups x 128 query-threads
#define NSPLIT   4            // M-dimension split inside the CTA
#define QPB      128          // queries per block
#define SCHUNK   512          // refs per subgroup tile (4 x 512 x 16B = 32KB)
#define MGW      (NSPLIT*KNN + 1)   // merge row stride (33) -> conflict-free

#define BUFSLOTS 16           // per-thread candidate buffer (smem, 64-bit packed)
#define FLUSH_AT 9            // flush when any lane has >= 9 (room for 8 more)

// smem layout (dynamic):
//   [0, UNION_BYTES):  phase1 = float4 tile[NSPLIT][SCHUNK] (32KB)
//                      phase2 = mgd[QPB][MGW] + mgi[QPB][MGW] (33792B)
//   [UNION_BYTES, +BUF_BYTES): u64 buf[BUFSLOTS][THREADS]
#define UNION_BYTES  (QPB * MGW * 4 * 2)              // 33792
#define BUF_BYTES    (BUFSLOTS * THREADS * 8)          // 65536
#define SMEM_TOTAL   (UNION_BYTES + BUF_BYTES)         // 99328

// Streaming top-8 insertion (sorted ascending; strict < keeps earlier index on
// ties, matching jax top_k tie order).
__device__ __forceinline__ void insert8(float (&bd)[KNN], int (&bi)[KNN], float d, int id) {
#pragma unroll
    for (int k = 0; k < KNN; k++) {
        if (d < bd[k]) {
            float td = bd[k]; int ti = bi[k];
            bd[k] = d; bi[k] = id;
            d = td; id = ti;
        }
    }
}

__global__ __launch_bounds__(THREADS, 2)
void knn_idw_kernel(const float* __restrict__ qpts,
                    const float* __restrict__ rpts,
                    const float* __restrict__ rflow,
                    float* __restrict__ out,
                    int N, int M)
{
    extern __shared__ char smem_raw[];
    float4* tile = (float4*)smem_raw;                       // [NSPLIT][SCHUNK]
    float*  mgd  = (float*)smem_raw;                        // [QPB][MGW]
    int*    mgi  = (int*)(smem_raw + QPB * MGW * 4);        // [QPB][MGW]
    unsigned long long* buf = (unsigned long long*)(smem_raw + UNION_BYTES);

    const int tid = threadIdx.x;
    const int sg  = tid >> 7;          // subgroup 0..3 (which M-quarter)
    const int qt  = tid & 127;         // query slot within block
    const int qi  = blockIdx.x * QPB + qt;

    float qx = 0.f, qy = 0.f, qz = 0.f;
    if (qi < N) {
        qx = qpts[3 * qi + 0];
        qy = qpts[3 * qi + 1];
        qz = qpts[3 * qi + 2];
    }
    // ranking key: s = |r|^2 - 2 q.r  (|q|^2 per-query constant, added in epilogue)
    const float ax = -2.f * qx, ay = -2.f * qy, az = -2.f * qz;

    const int Mper   = (M + NSPLIT - 1) / NSPLIT;
    const int mybase = sg * Mper;
    const int myend  = min(M, mybase + Mper);

    float bd[KNN]; int bi[KNN];
#pragma unroll
    for (int k = 0; k < KNN; k++) { bd[k] = FLT_MAX; bi[k] = 0; }
    float thr = FLT_MAX;   // stale copy of bd[7]; refreshed at flush (superset-safe)
    int nbuf = 0;

    for (int base = 0; base < Mper; base += SCHUNK) {
        const int gbase = mybase + base;
        const int cnt   = min(SCHUNK, myend - gbase);
        __syncthreads();
        for (int j = qt; j < cnt; j += 128) {
            const float* rp = rpts + 3 * (gbase + j);
            float x = __ldg(rp + 0);
            float y = __ldg(rp + 1);
            float z = __ldg(rp + 2);
            tile[sg * SCHUNK + j] = make_float4(x, y, z, fmaf(x, x, fmaf(y, y, z * z)));
        }
        __syncthreads();

        const float4* __restrict__ p = tile + sg * SCHUNK;
        int j = 0;
        for (; j + 8 <= cnt; j += 8) {
            float s[8];
#pragma unroll
            for (int u = 0; u < 8; u++) {
                float4 rp = p[j + u];                       // warp-broadcast LDS.128
                s[u] = fmaf(ax, rp.x, fmaf(ay, rp.y, fmaf(az, rp.z, rp.w)));
            }
            // branchless append of qualifying candidates (predicated STS.64)
#pragma unroll
            for (int u = 0; u < 8; u++) {
                if (s[u] < thr) {
                    unsigned long long v = (unsigned long long)__float_as_uint(s[u])
                                         | ((unsigned long long)(unsigned)(gbase + j + u) << 32);
                    buf[nbuf * THREADS + tid] = v;
                    nbuf++;
                }
            }
            // warp-uniform flush decision (no divergent branch in hot path)
            if (__any_sync(0xffffffffu, nbuf >= FLUSH_AT)) {
#pragma unroll 1
                for (int t = 0; t < nbuf; t++) {
                    unsigned long long v = buf[t * THREADS + tid];
                    float d  = __uint_as_float((unsigned)v);
                    int  id  = (int)(v >> 32);
                    if (d < bd[KNN - 1]) insert8(bd, bi, d, id);
                }
                nbuf = 0;
                thr = bd[KNN - 1];
            }
        }
        // remainder (not taken for M=16384; kept for generality)
        for (; j < cnt; j++) {
            float4 rp = p[j];
            float sv = fmaf(ax, rp.x, fmaf(ay, rp.y, fmaf(az, rp.z, rp.w)));
            if (sv < bd[KNN - 1]) insert8(bd, bi, sv, gbase + j);
        }
    }

    // final drain of leftover buffered candidates
#pragma unroll 1
    for (int t = 0; t < nbuf; t++) {
        unsigned long long v = buf[t * THREADS + tid];
        float d  = __uint_as_float((unsigned)v);
        int  id  = (int)(v >> 32);
        if (d < bd[KNN - 1]) insert8(bd, bi, d, id);
    }

    // ---- merge phase: publish 4 partial top-8 lists per query, subgroup 0 reduces ----
    __syncthreads();            // all tile reads done before union region is reused
#pragma unroll
    for (int k = 0; k < KNN; k++) {
        mgd[qt * MGW + sg * KNN + k] = bd[k];
        mgi[qt * MGW + sg * KNN + k] = bi[k];
    }
    __syncthreads();

    if (sg == 0 && qi < N) {
        float fd[KNN]; int fi[KNN];
#pragma unroll
        for (int k = 0; k < KNN; k++) { fd[k] = FLT_MAX; fi[k] = 0; }
        // ascending chunk order + strict < preserves lowest-index tie rule
#pragma unroll 4
        for (int c = 0; c < NSPLIT * KNN; c++) {
            float d = mgd[qt * MGW + c];
            if (d < fd[KNN - 1]) insert8(fd, fi, d, mgi[qt * MGW + c]);
        }

        // epilogue: d2 = s + |q|^2 (clamped), w = 1/(d2+eps)   [sqrt cancels: POWER==2]
        const float q2 = fmaf(qx, qx, fmaf(qy, qy, qz * qz));
        float sumw = 0.f, fx = 0.f, fy = 0.f, fz = 0.f;
#pragma unroll
        for (int k = 0; k < KNN; k++) {
            float d2 = fmaxf(fd[k] + q2, 0.0f);
            float w  = 1.0f / (d2 + 1e-8f);
            sumw += w;
            const float* f = rflow + 3 * fi[k];
            fx = fmaf(w, __ldg(f + 0), fx);
            fy = fmaf(w, __ldg(f + 1), fy);
            fz = fmaf(w, __ldg(f + 2), fz);
        }
        const float inv = 1.0f / sumw;
        out[3 * qi + 0] = fx * inv;
        out[3 * qi + 1] = fy * inv;
        out[3 * qi + 2] = fz * inv;
    }
}

extern "C" void kernel_launch(void* const* d_in, const int* in_sizes, int n_in,
                              void* d_out, int out_size)
{
    const float* qpts  = (const float*)d_in[0];   // [N,3] float32
    const float* rpts  = (const float*)d_in[1];   // [M,3] float32
    const float* rflow = (const float*)d_in[2];   // [M,3] float32
    float* out = (float*)d_out;                   // [N,3] float32

    const int N = in_sizes[0] / 3;
    const int M = in_sizes[1] / 3;

    cudaFuncSetAttribute(knn_idw_kernel,
                         cudaFuncAttributeMaxDynamicSharedMemorySize, SMEM_TOTAL);

    const int grid = (N + QPB - 1) / QPB;
    knn_idw_kernel<<<grid, THREADS, SMEM_TOTAL>>>(qpts, rpts, rflow, out, N, M);
}